// round 9
// baseline (speedup 1.0000x reference)
#include <cuda_runtime.h>

// Problem shape (fixed by reference setup_inputs): input/target (64, 2048, 80) fp32.
// Loss: for each element, 9 shifted abs-diffs (3x3 target neighborhood, OOB=0),
// smooth-min over the 9 via logsumexp(k=32), output = 0.5*(mean(center)+mean(smin)).
//
// R7: single fused kernel. Per-block partials -> last-block-done ticket does the
// deterministic fixed-order final sum (no trailing 8.4us grid=1 kernel).

constexpr int BATCH = 64;
constexpr int TLEN  = 2048;   // power of 2 -> row % TLEN via mask
constexpr int DIM   = 80;
constexpr int D4    = DIM / 4;                       // 20 float4 per row
constexpr int N4    = BATCH * TLEN * D4;             // 2,621,440 float4
constexpr long long NELEM = (long long)BATCH * TLEN * DIM;

constexpr int THREADS = 256;
constexpr int EPT     = 8;                           // float4s per thread
constexpr int GRID    = N4 / (THREADS * EPT);        // 1280 blocks, exact

__device__ float2 g_partials[GRID];                  // static scratch (no alloc)
__device__ unsigned int g_ticket;                    // zero-init; last block resets

__device__ __forceinline__ float fast_ex2(float x) {
    float y; asm("ex2.approx.ftz.f32 %0, %1;" : "=f"(y) : "f"(x)); return y;
}
__device__ __forceinline__ float fast_lg2(float x) {
    float y; asm("lg2.approx.ftz.f32 %0, %1;" : "=f"(y) : "f"(x)); return y;
}

__global__ __launch_bounds__(THREADS)
void jitter_main(const float* __restrict__ inp, const float* __restrict__ tgt,
                 float* __restrict__ out) {
    const float4* __restrict__ in4  = reinterpret_cast<const float4*>(inp);
    const float4* __restrict__ tg4  = reinterpret_cast<const float4*>(tgt);

    const float KE   = 46.16624131f;   // 32 * log2(e)
    const float IKE  = 0.02166085f;    // ln(2) / 32

    float accC = 0.f, accS = 0.f;

    int base = blockIdx.x * (THREADS * EPT) + threadIdx.x;

    #pragma unroll 2
    for (int k = 0; k < EPT; k++) {
        int i4  = base + k * THREADS;
        int row = i4 / D4;                 // global row = b*TLEN + t
        int d4  = i4 - row * D4;           // float4 index within row
        int t   = row & (TLEN - 1);

        float4 xi = in4[i4];

        // target neighborhood: 3 rows x 6 dims [d0-1 .. d0+4], zeros at boundaries
        float nm[6], nc[6], np6[6];
        {
            // center row (always valid)
            float4 c = tg4[row * D4 + d4];
            nc[1] = c.x; nc[2] = c.y; nc[3] = c.z; nc[4] = c.w;
            nc[0] = (d4 > 0)      ? tgt[row * DIM + d4 * 4 - 1] : 0.f;
            nc[5] = (d4 < D4 - 1) ? tgt[row * DIM + d4 * 4 + 4] : 0.f;
        }
        if (t > 0) {
            int r = row - 1;
            float4 c = tg4[r * D4 + d4];
            nm[1] = c.x; nm[2] = c.y; nm[3] = c.z; nm[4] = c.w;
            nm[0] = (d4 > 0)      ? tgt[r * DIM + d4 * 4 - 1] : 0.f;
            nm[5] = (d4 < D4 - 1) ? tgt[r * DIM + d4 * 4 + 4] : 0.f;
        } else {
            #pragma unroll
            for (int i = 0; i < 6; i++) nm[i] = 0.f;
        }
        if (t < TLEN - 1) {
            int r = row + 1;
            float4 c = tg4[r * D4 + d4];
            np6[1] = c.x; np6[2] = c.y; np6[3] = c.z; np6[4] = c.w;
            np6[0] = (d4 > 0)      ? tgt[r * DIM + d4 * 4 - 1] : 0.f;
            np6[5] = (d4 < D4 - 1) ? tgt[r * DIM + d4 * 4 + 4] : 0.f;
        } else {
            #pragma unroll
            for (int i = 0; i < 6; i++) np6[i] = 0.f;
        }

        float xv[4] = {xi.x, xi.y, xi.z, xi.w};

        #pragma unroll
        for (int j = 0; j < 4; j++) {
            float x  = xv[j];
            // 9 shifted abs-diffs: diff(dt,dd) = |x - tgt[t+dt][d+dd]|
            float d0 = fabsf(x - nc [j + 1]);   // ( 0, 0)  center
            float d1 = fabsf(x - np6[j + 1]);   // (+1, 0)
            float d2 = fabsf(x - nm [j + 1]);   // (-1, 0)
            float d3 = fabsf(x - nc [j + 2]);   // ( 0,+1)
            float d4v= fabsf(x - nc [j    ]);   // ( 0,-1)
            float d5 = fabsf(x - np6[j + 2]);   // (+1,+1)
            float d6 = fabsf(x - nm [j    ]);   // (-1,-1)
            float d7 = fabsf(x - np6[j    ]);   // (+1,-1)
            float d8 = fabsf(x - nm [j + 2]);   // (-1,+1)

            float m = fminf(fminf(fminf(d0, d1), fminf(d2, d3)),
                            fminf(fminf(fminf(d4v, d5), fminf(d6, d7)), d8));

            float S = fast_ex2((m - d0 ) * KE) + fast_ex2((m - d1) * KE)
                    + fast_ex2((m - d2 ) * KE) + fast_ex2((m - d3) * KE)
                    + fast_ex2((m - d4v) * KE) + fast_ex2((m - d5) * KE)
                    + fast_ex2((m - d6 ) * KE) + fast_ex2((m - d7) * KE)
                    + fast_ex2((m - d8 ) * KE);

            float sm = m - fast_lg2(S) * IKE;

            accC += d0;
            accS += sm;
        }
    }

    // warp reduce
    #pragma unroll
    for (int o = 16; o; o >>= 1) {
        accC += __shfl_xor_sync(0xFFFFFFFFu, accC, o);
        accS += __shfl_xor_sync(0xFFFFFFFFu, accS, o);
    }

    __shared__ float sC[8], sS[8];
    __shared__ bool  sLast;
    int lane = threadIdx.x & 31;
    int wid  = threadIdx.x >> 5;
    if (lane == 0) { sC[wid] = accC; sS[wid] = accS; }
    __syncthreads();

    if (threadIdx.x == 0) {
        float c = 0.f, s = 0.f;
        #pragma unroll
        for (int i = 0; i < 8; i++) { c += sC[i]; s += sS[i]; }
        g_partials[blockIdx.x] = make_float2(c, s);
        __threadfence();                               // publish partial
        unsigned int t = atomicAdd(&g_ticket, 1u);
        sLast = (t == (unsigned int)(GRID - 1));
    }
    __syncthreads();

    if (!sLast) return;

    // ---- last block: deterministic fixed-order final reduction ----
    double c = 0.0, s = 0.0;
    #pragma unroll
    for (int i = threadIdx.x; i < GRID; i += THREADS) {   // fixed assignment
        float2 p = g_partials[i];
        c += (double)p.x;
        s += (double)p.y;
    }
    #pragma unroll
    for (int o = 16; o; o >>= 1) {
        c += __shfl_xor_sync(0xFFFFFFFFu, c, o);
        s += __shfl_xor_sync(0xFFFFFFFFu, s, o);
    }
    __shared__ double dC[8], dS[8];
    if (lane == 0) { dC[wid] = c; dS[wid] = s; }
    __syncthreads();
    if (threadIdx.x == 0) {
        double tc = 0.0, ts = 0.0;
        #pragma unroll
        for (int i = 0; i < 8; i++) { tc += dC[i]; ts += dS[i]; }
        out[0] = (float)(0.5 * (tc + ts) / (double)NELEM);
        g_ticket = 0u;                                  // reset for next replay
    }
}

extern "C" void kernel_launch(void* const* d_in, const int* in_sizes, int n_in,
                              void* d_out, int out_size) {
    const float* inp = (const float*)d_in[0];
    const float* tgt = (const float*)d_in[1];
    float* out = (float*)d_out;
    jitter_main<<<GRID, THREADS>>>(inp, tgt, out);
}

// round 12
// speedup vs baseline: 1.6055x; 1.6055x over previous
#include <cuda_runtime.h>

// Problem shape (fixed by reference setup_inputs): input/target (64, 2048, 80) fp32.
// Loss: for each element, 9 shifted abs-diffs (3x3 target neighborhood, OOB=0),
// smooth-min over the 9 via logsumexp(k=32), output = 0.5*(mean(center)+mean(smin)).
//
// R10: single fused kernel, ALL-FLOAT tail (R9's double-precision tail dragged
// register allocation to 48 regs and spilled the main loop's neighborhood
// arrays -> L1 39.6%, 2x issue traffic, 53.8us). Fixed-order float reduction
// is deterministic and well within the 1e-3 threshold.

constexpr int BATCH = 64;
constexpr int TLEN  = 2048;   // power of 2 -> row % TLEN via mask
constexpr int DIM   = 80;
constexpr int D4    = DIM / 4;                       // 20 float4 per row
constexpr int N4    = BATCH * TLEN * D4;             // 2,621,440 float4
constexpr float INV_NELEM = 1.0f / (float)((long long)BATCH * TLEN * DIM);

constexpr int THREADS = 256;
constexpr int EPT     = 8;                           // float4s per thread
constexpr int GRID    = N4 / (THREADS * EPT);        // 1280 blocks, exact

__device__ float2 g_partials[GRID];                  // static scratch (no alloc)
__device__ unsigned int g_ticket;                    // zero-init; last block resets

__device__ __forceinline__ float fast_ex2(float x) {
    float y; asm("ex2.approx.ftz.f32 %0, %1;" : "=f"(y) : "f"(x)); return y;
}
__device__ __forceinline__ float fast_lg2(float x) {
    float y; asm("lg2.approx.ftz.f32 %0, %1;" : "=f"(y) : "f"(x)); return y;
}

__global__ __launch_bounds__(THREADS)
void jitter_main(const float* __restrict__ inp, const float* __restrict__ tgt,
                 float* __restrict__ out) {
    const float4* __restrict__ in4  = reinterpret_cast<const float4*>(inp);
    const float4* __restrict__ tg4  = reinterpret_cast<const float4*>(tgt);

    const float KE   = 46.16624131f;   // 32 * log2(e)
    const float IKE  = 0.02166085f;    // ln(2) / 32

    float accC = 0.f, accS = 0.f;

    int base = blockIdx.x * (THREADS * EPT) + threadIdx.x;

    #pragma unroll 2
    for (int k = 0; k < EPT; k++) {
        int i4  = base + k * THREADS;
        int row = i4 / D4;                 // global row = b*TLEN + t
        int d4  = i4 - row * D4;           // float4 index within row
        int t   = row & (TLEN - 1);

        float4 xi = in4[i4];

        // target neighborhood: 3 rows x 6 dims [d0-1 .. d0+4], zeros at boundaries
        float nm[6], nc[6], np6[6];
        {
            // center row (always valid)
            float4 c = tg4[row * D4 + d4];
            nc[1] = c.x; nc[2] = c.y; nc[3] = c.z; nc[4] = c.w;
            nc[0] = (d4 > 0)      ? tgt[row * DIM + d4 * 4 - 1] : 0.f;
            nc[5] = (d4 < D4 - 1) ? tgt[row * DIM + d4 * 4 + 4] : 0.f;
        }
        if (t > 0) {
            int r = row - 1;
            float4 c = tg4[r * D4 + d4];
            nm[1] = c.x; nm[2] = c.y; nm[3] = c.z; nm[4] = c.w;
            nm[0] = (d4 > 0)      ? tgt[r * DIM + d4 * 4 - 1] : 0.f;
            nm[5] = (d4 < D4 - 1) ? tgt[r * DIM + d4 * 4 + 4] : 0.f;
        } else {
            #pragma unroll
            for (int i = 0; i < 6; i++) nm[i] = 0.f;
        }
        if (t < TLEN - 1) {
            int r = row + 1;
            float4 c = tg4[r * D4 + d4];
            np6[1] = c.x; np6[2] = c.y; np6[3] = c.z; np6[4] = c.w;
            np6[0] = (d4 > 0)      ? tgt[r * DIM + d4 * 4 - 1] : 0.f;
            np6[5] = (d4 < D4 - 1) ? tgt[r * DIM + d4 * 4 + 4] : 0.f;
        } else {
            #pragma unroll
            for (int i = 0; i < 6; i++) np6[i] = 0.f;
        }

        float xv[4] = {xi.x, xi.y, xi.z, xi.w};

        #pragma unroll
        for (int j = 0; j < 4; j++) {
            float x  = xv[j];
            // 9 shifted abs-diffs: diff(dt,dd) = |x - tgt[t+dt][d+dd]|
            float d0 = fabsf(x - nc [j + 1]);   // ( 0, 0)  center
            float d1 = fabsf(x - np6[j + 1]);   // (+1, 0)
            float d2 = fabsf(x - nm [j + 1]);   // (-1, 0)
            float d3 = fabsf(x - nc [j + 2]);   // ( 0,+1)
            float d4v= fabsf(x - nc [j    ]);   // ( 0,-1)
            float d5 = fabsf(x - np6[j + 2]);   // (+1,+1)
            float d6 = fabsf(x - nm [j    ]);   // (-1,-1)
            float d7 = fabsf(x - np6[j    ]);   // (+1,-1)
            float d8 = fabsf(x - nm [j + 2]);   // (-1,+1)

            float m = fminf(fminf(fminf(d0, d1), fminf(d2, d3)),
                            fminf(fminf(fminf(d4v, d5), fminf(d6, d7)), d8));

            float S = fast_ex2((m - d0 ) * KE) + fast_ex2((m - d1) * KE)
                    + fast_ex2((m - d2 ) * KE) + fast_ex2((m - d3) * KE)
                    + fast_ex2((m - d4v) * KE) + fast_ex2((m - d5) * KE)
                    + fast_ex2((m - d6 ) * KE) + fast_ex2((m - d7) * KE)
                    + fast_ex2((m - d8 ) * KE);

            float sm = m - fast_lg2(S) * IKE;

            accC += d0;
            accS += sm;
        }
    }

    // warp reduce
    #pragma unroll
    for (int o = 16; o; o >>= 1) {
        accC += __shfl_xor_sync(0xFFFFFFFFu, accC, o);
        accS += __shfl_xor_sync(0xFFFFFFFFu, accS, o);
    }

    __shared__ float sC[8], sS[8];
    __shared__ bool  sLast;
    int lane = threadIdx.x & 31;
    int wid  = threadIdx.x >> 5;
    if (lane == 0) { sC[wid] = accC; sS[wid] = accS; }
    __syncthreads();

    if (threadIdx.x == 0) {
        float c = 0.f, s = 0.f;
        #pragma unroll
        for (int i = 0; i < 8; i++) { c += sC[i]; s += sS[i]; }
        g_partials[blockIdx.x] = make_float2(c, s);
        __threadfence();                               // publish partial
        unsigned int t = atomicAdd(&g_ticket, 1u);
        sLast = (t == (unsigned int)(GRID - 1));
    }
    __syncthreads();

    if (!sLast) return;

    // ---- last block: deterministic fixed-order ALL-FLOAT final reduction ----
    float c = 0.f, s = 0.f;
    #pragma unroll 1
    for (int i = threadIdx.x; i < GRID; i += THREADS) {   // fixed assignment
        float2 p = g_partials[i];
        c += p.x;
        s += p.y;
    }
    #pragma unroll
    for (int o = 16; o; o >>= 1) {
        c += __shfl_xor_sync(0xFFFFFFFFu, c, o);
        s += __shfl_xor_sync(0xFFFFFFFFu, s, o);
    }
    if (lane == 0) { sC[wid] = c; sS[wid] = s; }
    __syncthreads();
    if (threadIdx.x == 0) {
        float tc = 0.f, ts = 0.f;
        #pragma unroll
        for (int i = 0; i < 8; i++) { tc += sC[i]; ts += sS[i]; }
        out[0] = 0.5f * (tc + ts) * INV_NELEM;
        g_ticket = 0u;                                  // reset for next replay
    }
}

extern "C" void kernel_launch(void* const* d_in, const int* in_sizes, int n_in,
                              void* d_out, int out_size) {
    const float* inp = (const float*)d_in[0];
    const float* tgt = (const float*)d_in[1];
    float* out = (float*)d_out;
    jitter_main<<<GRID, THREADS>>>(inp, tgt, out);
}

// round 13
// speedup vs baseline: 1.8432x; 1.1480x over previous
#include <cuda_runtime.h>

// Problem shape (fixed by reference setup_inputs): input/target (64, 2048, 80) fp32.
// Loss: for each element, 9 shifted abs-diffs (3x3 target neighborhood, OOB=0),
// smooth-min over the 9 via logsumexp(k=32), output = 0.5*(mean(center)+mean(smin)).
//
// R13: (a) persistent grid (740 = 148 SM x 5 CTA) + grid-stride -> no wave
// quantization (R12: 1280 blocks / 740 slots = 1.73 waves, 2nd wave 73% idle).
// __launch_bounds__(256,5) pins regs<=48 so 5 CTA/SM holds.
// (b) logsumexp args as single FFMA each: arg = fma(d, -KE, m*KE) instead of
// (m-d)*KE (FADD+FMUL) -> saves ~8 issue slots/element.

constexpr int BATCH = 64;
constexpr int TLEN  = 2048;   // power of 2 -> t via mask
constexpr int DIM   = 80;
constexpr int D4    = DIM / 4;                       // 20 float4 per row
constexpr int N4    = BATCH * TLEN * D4;             // 2,621,440 float4
constexpr float INV_NELEM = 1.0f / (float)((long long)BATCH * TLEN * DIM);

constexpr int THREADS = 256;
constexpr int GRID    = 740;                         // 148 SMs x 5 resident CTAs
constexpr int STRIDE  = GRID * THREADS;              // grid-stride

__device__ float2 g_partials[GRID];                  // static scratch (no alloc)
__device__ unsigned int g_ticket;                    // zero-init; last block resets

__device__ __forceinline__ float fast_ex2(float x) {
    float y; asm("ex2.approx.ftz.f32 %0, %1;" : "=f"(y) : "f"(x)); return y;
}
__device__ __forceinline__ float fast_lg2(float x) {
    float y; asm("lg2.approx.ftz.f32 %0, %1;" : "=f"(y) : "f"(x)); return y;
}

__global__ __launch_bounds__(THREADS, 5)
void jitter_main(const float* __restrict__ inp, const float* __restrict__ tgt,
                 float* __restrict__ out) {
    const float4* __restrict__ in4  = reinterpret_cast<const float4*>(inp);
    const float4* __restrict__ tg4  = reinterpret_cast<const float4*>(tgt);

    const float KE   = 46.16624131f;   // 32 * log2(e)
    const float IKE  = 0.02166085f;    // ln(2) / 32

    float accC = 0.f, accS = 0.f;

    #pragma unroll 2
    for (int i4 = blockIdx.x * THREADS + threadIdx.x; i4 < N4; i4 += STRIDE) {
        int row = i4 / D4;                 // global row = b*TLEN + t
        int d4  = i4 - row * D4;           // float4 index within row
        int t   = row & (TLEN - 1);

        float4 xi = in4[i4];

        // target neighborhood: 3 rows x 6 dims [d0-1 .. d0+4], zeros at boundaries
        float nm[6], nc[6], np6[6];
        {
            // center row (always valid)
            float4 c = tg4[row * D4 + d4];
            nc[1] = c.x; nc[2] = c.y; nc[3] = c.z; nc[4] = c.w;
            nc[0] = (d4 > 0)      ? tgt[row * DIM + d4 * 4 - 1] : 0.f;
            nc[5] = (d4 < D4 - 1) ? tgt[row * DIM + d4 * 4 + 4] : 0.f;
        }
        if (t > 0) {
            int r = row - 1;
            float4 c = tg4[r * D4 + d4];
            nm[1] = c.x; nm[2] = c.y; nm[3] = c.z; nm[4] = c.w;
            nm[0] = (d4 > 0)      ? tgt[r * DIM + d4 * 4 - 1] : 0.f;
            nm[5] = (d4 < D4 - 1) ? tgt[r * DIM + d4 * 4 + 4] : 0.f;
        } else {
            #pragma unroll
            for (int i = 0; i < 6; i++) nm[i] = 0.f;
        }
        if (t < TLEN - 1) {
            int r = row + 1;
            float4 c = tg4[r * D4 + d4];
            np6[1] = c.x; np6[2] = c.y; np6[3] = c.z; np6[4] = c.w;
            np6[0] = (d4 > 0)      ? tgt[r * DIM + d4 * 4 - 1] : 0.f;
            np6[5] = (d4 < D4 - 1) ? tgt[r * DIM + d4 * 4 + 4] : 0.f;
        } else {
            #pragma unroll
            for (int i = 0; i < 6; i++) np6[i] = 0.f;
        }

        float xv[4] = {xi.x, xi.y, xi.z, xi.w};

        #pragma unroll
        for (int j = 0; j < 4; j++) {
            float x  = xv[j];
            // 9 shifted abs-diffs: diff(dt,dd) = |x - tgt[t+dt][d+dd]|
            float d0 = fabsf(x - nc [j + 1]);   // ( 0, 0)  center
            float d1 = fabsf(x - np6[j + 1]);   // (+1, 0)
            float d2 = fabsf(x - nm [j + 1]);   // (-1, 0)
            float d3 = fabsf(x - nc [j + 2]);   // ( 0,+1)
            float d4v= fabsf(x - nc [j    ]);   // ( 0,-1)
            float d5 = fabsf(x - np6[j + 2]);   // (+1,+1)
            float d6 = fabsf(x - nm [j    ]);   // (-1,-1)
            float d7 = fabsf(x - np6[j    ]);   // (+1,-1)
            float d8 = fabsf(x - nm [j + 2]);   // (-1,+1)

            float m = fminf(fminf(fminf(d0, d1), fminf(d2, d3)),
                            fminf(fminf(fminf(d4v, d5), fminf(d6, d7)), d8));

            // logsumexp terms: arg_i = (m - d_i)*KE computed as one FFMA each.
            // At the argmin term the arg is ~ulp(mK) instead of exactly 0
            // -> ex2 within 1e-5 of 1, negligible vs 1e-3 threshold.
            float mK = m * KE;
            float S = fast_ex2(fmaf(d0 , -KE, mK)) + fast_ex2(fmaf(d1, -KE, mK))
                    + fast_ex2(fmaf(d2 , -KE, mK)) + fast_ex2(fmaf(d3, -KE, mK))
                    + fast_ex2(fmaf(d4v, -KE, mK)) + fast_ex2(fmaf(d5, -KE, mK))
                    + fast_ex2(fmaf(d6 , -KE, mK)) + fast_ex2(fmaf(d7, -KE, mK))
                    + fast_ex2(fmaf(d8 , -KE, mK));

            float sm = fmaf(fast_lg2(S), -IKE, m);

            accC += d0;
            accS += sm;
        }
    }

    // warp reduce
    #pragma unroll
    for (int o = 16; o; o >>= 1) {
        accC += __shfl_xor_sync(0xFFFFFFFFu, accC, o);
        accS += __shfl_xor_sync(0xFFFFFFFFu, accS, o);
    }

    __shared__ float sC[8], sS[8];
    __shared__ bool  sLast;
    int lane = threadIdx.x & 31;
    int wid  = threadIdx.x >> 5;
    if (lane == 0) { sC[wid] = accC; sS[wid] = accS; }
    __syncthreads();

    if (threadIdx.x == 0) {
        float c = 0.f, s = 0.f;
        #pragma unroll
        for (int i = 0; i < 8; i++) { c += sC[i]; s += sS[i]; }
        g_partials[blockIdx.x] = make_float2(c, s);
        __threadfence();                               // publish partial
        unsigned int t = atomicAdd(&g_ticket, 1u);
        sLast = (t == (unsigned int)(GRID - 1));
    }
    __syncthreads();

    if (!sLast) return;

    // ---- last block: deterministic fixed-order ALL-FLOAT final reduction ----
    float c = 0.f, s = 0.f;
    #pragma unroll 1
    for (int i = threadIdx.x; i < GRID; i += THREADS) {   // fixed assignment
        float2 p = g_partials[i];
        c += p.x;
        s += p.y;
    }
    #pragma unroll
    for (int o = 16; o; o >>= 1) {
        c += __shfl_xor_sync(0xFFFFFFFFu, c, o);
        s += __shfl_xor_sync(0xFFFFFFFFu, s, o);
    }
    if (lane == 0) { sC[wid] = c; sS[wid] = s; }
    __syncthreads();
    if (threadIdx.x == 0) {
        float tc = 0.f, ts = 0.f;
        #pragma unroll
        for (int i = 0; i < 8; i++) { tc += sC[i]; ts += sS[i]; }
        out[0] = 0.5f * (tc + ts) * INV_NELEM;
        g_ticket = 0u;                                  // reset for next replay
    }
}

extern "C" void kernel_launch(void* const* d_in, const int* in_sizes, int n_in,
                              void* d_out, int out_size) {
    const float* inp = (const float*)d_in[0];
    const float* tgt = (const float*)d_in[1];
    float* out = (float*)d_out;
    jitter_main<<<GRID, THREADS>>>(inp, tgt, out);
}